// round 2
// baseline (speedup 1.0000x reference)
#include <cuda_runtime.h>
#include <math_constants.h>

#define C 128
#define MAXN 50000

// Scratch: per-(node,channel) segment max of x[src] over incoming edges.
__device__ float g_seg[MAXN * C];

__global__ void init_seg(int total) {
    int i = blockIdx.x * blockDim.x + threadIdx.x;
    int stride = gridDim.x * blockDim.x;
    for (; i < total; i += stride) g_seg[i] = -CUDART_INF_F;
}

// float atomic max via signed/unsigned reinterpretation (compiles to RED, no return).
// Sign-bit dispatch so +/-0.0 are ordered correctly.
__device__ __forceinline__ void atomicMaxF(float* a, float v) {
    unsigned int uv = __float_as_uint(v);
    if ((uv >> 31) == 0) {
        atomicMax((int*)a, (int)uv);            // non-negative: int order == float order
    } else {
        atomicMin((unsigned int*)a, uv);        // negative: uint order is reversed float order
    }
}

// One warp per edge: gather x[src] row (512B coalesced, L2-resident) and
// scatter 128 RED-max ops into g_seg[dst].
__global__ void edge_scatter(const float* __restrict__ x,
                             const int* __restrict__ ei,
                             int E) {
    int gw = (int)((blockIdx.x * (unsigned)blockDim.x + threadIdx.x) >> 5);
    int lane = threadIdx.x & 31;
    if (gw >= E) return;

    int src = ei[gw];              // uniform within warp -> single broadcast request
    int dst = ei[E + gw];

    float4 v = reinterpret_cast<const float4*>(x + (size_t)src * C)[lane];
    float* base = g_seg + (size_t)dst * C + lane * 4;
    atomicMaxF(base + 0, v.x);
    atomicMaxF(base + 1, v.y);
    atomicMaxF(base + 2, v.z);
    atomicMaxF(base + 3, v.w);
}

// Fused epilogue GEMM:
//   cat[n] = [ x[n] (k<128)  |  (seg[n]==-inf ? 0 : seg[n]-x[n]) (k>=128) ]
//   out[n] = cat[n] @ W + b
// Tile: 64 rows x 128 cols per block; thread (tx,ty) in (32,8) computes
// 8 rows x 4 cols in registers.
__global__ void fused_gemm(const float* __restrict__ x,
                           const float* __restrict__ W,
                           const float* __restrict__ b,
                           float* __restrict__ out, int N) {
    __shared__ float cat_s[64][33];       // +1 pad to dodge bank conflicts
    __shared__ float w_s[32][128];

    int tx = threadIdx.x;                 // 0..31  -> out cols tx*4..tx*4+3
    int ty = threadIdx.y;                 // 0..7   -> rows ty*8..ty*8+7
    int t  = ty * 32 + tx;                // 0..255
    int row0 = blockIdx.x * 64;

    float4 acc[8];
#pragma unroll
    for (int i = 0; i < 8; i++) acc[i] = make_float4(0.f, 0.f, 0.f, 0.f);

#pragma unroll 1
    for (int c = 0; c < 8; c++) {         // 8 k-chunks of 32 -> K=256
        int k0 = c * 32;

        // Stage W chunk: 32 x 128 floats = 1024 float4, 4 per thread.
#pragma unroll
        for (int it = 0; it < 4; it++) {
            int idx = t + 256 * it;       // 0..1023
            int kk = idx >> 5;            // 0..31 (k row in chunk)
            int jj = idx & 31;            // float4 column
            float4 wv = reinterpret_cast<const float4*>(W + (size_t)(k0 + kk) * 128)[jj];
            reinterpret_cast<float4*>(&w_s[kk][0])[jj] = wv;
        }

        // Stage cat chunk: 64 rows x 32 k, 8 scalars per thread (coalesced per row segment).
#pragma unroll
        for (int it = 0; it < 8; it++) {
            int idx = t + 256 * it;       // 0..2047
            int r = idx >> 5;             // row within tile
            int k = idx & 31;
            int row = row0 + r;
            float val = 0.f;
            if (row < N) {
                if (k0 < 128) {
                    val = x[(size_t)row * C + k0 + k];
                } else {
                    int kk = k0 - 128 + k;
                    float s = g_seg[(size_t)row * C + kk];
                    val = (s == -CUDART_INF_F) ? 0.f : s - x[(size_t)row * C + kk];
                }
            }
            cat_s[r][k] = val;
        }
        __syncthreads();

#pragma unroll
        for (int k = 0; k < 32; k++) {
            float4 wv = reinterpret_cast<const float4*>(&w_s[k][0])[tx];
#pragma unroll
            for (int i = 0; i < 8; i++) {
                float cv = cat_s[ty * 8 + i][k];   // smem broadcast across tx
                acc[i].x += cv * wv.x;
                acc[i].y += cv * wv.y;
                acc[i].z += cv * wv.z;
                acc[i].w += cv * wv.w;
            }
        }
        __syncthreads();
    }

    float4 bv = reinterpret_cast<const float4*>(b)[tx];
#pragma unroll
    for (int i = 0; i < 8; i++) {
        int row = row0 + ty * 8 + i;
        if (row < N) {
            float4 o;
            o.x = acc[i].x + bv.x;
            o.y = acc[i].y + bv.y;
            o.z = acc[i].z + bv.z;
            o.w = acc[i].w + bv.w;
            reinterpret_cast<float4*>(out + (size_t)row * C)[tx] = o;
        }
    }
}

extern "C" void kernel_launch(void* const* d_in, const int* in_sizes, int n_in,
                              void* d_out, int out_size) {
    const float* x   = (const float*)d_in[0];
    const int*   ei  = (const int*)d_in[1];
    const float* W   = (const float*)d_in[2];
    const float* b   = (const float*)d_in[3];
    float*       out = (float*)d_out;

    int N = in_sizes[0] / C;      // 50000
    int E = in_sizes[1] / 2;      // 800000

    // 1) seg = -inf
    {
        int total = N * C;
        int blocks = (total + 255) / 256;
        if (blocks > 4096) blocks = 4096;   // grid-stride
        init_seg<<<blocks, 256>>>(total);
    }

    // 2) segment max of x[src] over dst (warp per edge)
    {
        long long threads = (long long)E * 32;
        int blocks = (int)((threads + 255) / 256);
        edge_scatter<<<blocks, 256>>>(x, ei, E);
    }

    // 3) fused concat + GEMM + bias
    {
        dim3 bdim(32, 8);
        int blocks = (N + 63) / 64;
        fused_gemm<<<blocks, bdim>>>(x, W, b, out, N);
    }
}

// round 3
// speedup vs baseline: 2.1573x; 2.1573x over previous
#include <cuda_runtime.h>
#include <math_constants.h>

#define C 128
#define MAXN 50000
#define MAXE 800000
#define SCAN_T 1024

// CSR scratch
__device__ int   g_cnt[MAXN];        // counts, then reused as fill cursors
__device__ int   g_off[MAXN + 1];   // exclusive offsets
__device__ int   g_srcs[MAXE];      // src node ids grouped by dst
__device__ float g_mdiff[MAXN * C]; // max_{src->n}(x[src]) - x[n], or 0 if no in-edges

__global__ void zero_counts(int N) {
    int i = blockIdx.x * blockDim.x + threadIdx.x;
    if (i < N) g_cnt[i] = 0;
}

__global__ void count_deg(const int* __restrict__ ei, int E) {
    int i = blockIdx.x * blockDim.x + threadIdx.x;
    if (i < E) atomicAdd(&g_cnt[ei[E + i]], 1);
}

// Single-block exclusive scan over N counts (chunked + Hillis-Steele on partials).
// Also zeroes g_cnt for reuse as cursors.
__global__ void scan_offsets(int N) {
    __shared__ int part[SCAN_T];
    int t = threadIdx.x;
    int chunk = (N + SCAN_T - 1) / SCAN_T;
    int lo = t * chunk;
    int hi = min(lo + chunk, N);

    int s = 0;
    for (int i = lo; i < hi; i++) s += g_cnt[i];
    part[t] = s;
    __syncthreads();

    // inclusive Hillis-Steele on partials
    for (int d = 1; d < SCAN_T; d <<= 1) {
        int v = (t >= d) ? part[t - d] : 0;
        __syncthreads();
        part[t] += v;
        __syncthreads();
    }

    int run = (t == 0) ? 0 : part[t - 1];   // exclusive base for this chunk
    for (int i = lo; i < hi; i++) {
        int c = g_cnt[i];
        g_off[i] = run;
        run += c;
        g_cnt[i] = 0;                        // reset cursor
    }
    if (hi == N && lo <= N) g_off[N] = run;  // last covering thread writes total
}

__global__ void fill_csr(const int* __restrict__ ei, int E) {
    int i = blockIdx.x * blockDim.x + threadIdx.x;
    if (i < E) {
        int dst = ei[E + i];
        int pos = g_off[dst] + atomicAdd(&g_cnt[dst], 1);
        g_srcs[pos] = ei[i];
    }
}

// Warp per node: max-reduce incoming x[src] rows, subtract x[n], write maxdiff.
__global__ void node_max(const float* __restrict__ x, int N) {
    int warp = (int)((blockIdx.x * (unsigned)blockDim.x + threadIdx.x) >> 5);
    int lane = threadIdx.x & 31;
    if (warp >= N) return;

    int begin = g_off[warp];
    int end   = g_off[warp + 1];

    float4 acc = make_float4(-CUDART_INF_F, -CUDART_INF_F, -CUDART_INF_F, -CUDART_INF_F);

    for (int base = base = begin; base < end; base += 32) {
        int j = base + lane;
        int s = (j < end) ? g_srcs[j] : 0;
        int cnt = min(end - base, 32);
        for (int t = 0; t < cnt; t++) {
            int src = __shfl_sync(0xffffffffu, s, t);
            float4 v = reinterpret_cast<const float4*>(x + (size_t)src * C)[lane];
            acc.x = fmaxf(acc.x, v.x);
            acc.y = fmaxf(acc.y, v.y);
            acc.z = fmaxf(acc.z, v.z);
            acc.w = fmaxf(acc.w, v.w);
        }
    }

    float4 o;
    if (end > begin) {
        float4 xn = reinterpret_cast<const float4*>(x + (size_t)warp * C)[lane];
        o.x = acc.x - xn.x;
        o.y = acc.y - xn.y;
        o.z = acc.z - xn.z;
        o.w = acc.w - xn.w;
    } else {
        o = make_float4(0.f, 0.f, 0.f, 0.f);
    }
    reinterpret_cast<float4*>(g_mdiff + (size_t)warp * C)[lane] = o;
}

// Fused GEMM: out[n] = [x[n] | mdiff[n]] @ W + b
// Tile: 64 rows x 128 cols per block; thread (tx,ty) in (32,8) -> 8 rows x 4 cols.
__global__ void fused_gemm(const float* __restrict__ x,
                           const float* __restrict__ W,
                           const float* __restrict__ b,
                           float* __restrict__ out, int N) {
    __shared__ float cat_s[64][33];
    __shared__ float w_s[32][128];

    int tx = threadIdx.x;
    int ty = threadIdx.y;
    int t  = ty * 32 + tx;
    int row0 = blockIdx.x * 64;

    float4 acc[8];
#pragma unroll
    for (int i = 0; i < 8; i++) acc[i] = make_float4(0.f, 0.f, 0.f, 0.f);

#pragma unroll 1
    for (int c = 0; c < 8; c++) {
        int k0 = c * 32;

#pragma unroll
        for (int it = 0; it < 4; it++) {
            int idx = t + 256 * it;
            int kk = idx >> 5;
            int jj = idx & 31;
            float4 wv = reinterpret_cast<const float4*>(W + (size_t)(k0 + kk) * 128)[jj];
            reinterpret_cast<float4*>(&w_s[kk][0])[jj] = wv;
        }

#pragma unroll
        for (int it = 0; it < 8; it++) {
            int idx = t + 256 * it;
            int r = idx >> 5;
            int k = idx & 31;
            int row = row0 + r;
            float val = 0.f;
            if (row < N) {
                if (k0 < 128) val = x[(size_t)row * C + k0 + k];
                else          val = g_mdiff[(size_t)row * C + (k0 - 128) + k];
            }
            cat_s[r][k] = val;
        }
        __syncthreads();

#pragma unroll
        for (int k = 0; k < 32; k++) {
            float4 wv = reinterpret_cast<const float4*>(&w_s[k][0])[tx];
#pragma unroll
            for (int i = 0; i < 8; i++) {
                float cv = cat_s[ty * 8 + i][k];
                acc[i].x += cv * wv.x;
                acc[i].y += cv * wv.y;
                acc[i].z += cv * wv.z;
                acc[i].w += cv * wv.w;
            }
        }
        __syncthreads();
    }

    float4 bv = reinterpret_cast<const float4*>(b)[tx];
#pragma unroll
    for (int i = 0; i < 8; i++) {
        int row = row0 + ty * 8 + i;
        if (row < N) {
            float4 o;
            o.x = acc[i].x + bv.x;
            o.y = acc[i].y + bv.y;
            o.z = acc[i].z + bv.z;
            o.w = acc[i].w + bv.w;
            reinterpret_cast<float4*>(out + (size_t)row * C)[tx] = o;
        }
    }
}

extern "C" void kernel_launch(void* const* d_in, const int* in_sizes, int n_in,
                              void* d_out, int out_size) {
    const float* x   = (const float*)d_in[0];
    const int*   ei  = (const int*)d_in[1];
    const float* W   = (const float*)d_in[2];
    const float* b   = (const float*)d_in[3];
    float*       out = (float*)d_out;

    int N = in_sizes[0] / C;      // 50000
    int E = in_sizes[1] / 2;      // 800000

    zero_counts<<<(N + 255) / 256, 256>>>(N);
    count_deg<<<(E + 255) / 256, 256>>>(ei, E);
    scan_offsets<<<1, SCAN_T>>>(N);
    fill_csr<<<(E + 255) / 256, 256>>>(ei, E);

    {
        long long threads = (long long)N * 32;
        int blocks = (int)((threads + 255) / 256);
        node_max<<<blocks, 256>>>(x, N);
    }
    {
        dim3 bdim(32, 8);
        fused_gemm<<<(N + 63) / 64, bdim>>>(x, W, b, out, N);
    }
}

// round 5
// speedup vs baseline: 2.6065x; 1.2083x over previous
#include <cuda_runtime.h>
#include <cuda_bf16.h>
#include <math_constants.h>
#include <cstdint>

#define C 128
#define MAXN 50000
#define MAXE 800000
#define SCAN_T 1024
#define KTOT 256

// CSR scratch
__device__ int   g_cnt[MAXN];
__device__ int   g_off[MAXN + 1];
__device__ int   g_srcs[MAXE];
__device__ float g_mdiff[MAXN * C];
// Split-precision W (hi/lo bf16), stored as raw 16-bit words
__device__ unsigned short g_Whi[KTOT * C];
__device__ unsigned short g_Wlo[KTOT * C];

__global__ void zero_counts(int N) {
    int i = blockIdx.x * blockDim.x + threadIdx.x;
    if (i < N) g_cnt[i] = 0;
}

__global__ void count_deg(const int* __restrict__ ei, int E) {
    int i = blockIdx.x * blockDim.x + threadIdx.x;
    if (i < E) atomicAdd(&g_cnt[ei[E + i]], 1);
}

__global__ void scan_offsets(int N) {
    __shared__ int part[SCAN_T];
    int t = threadIdx.x;
    int chunk = (N + SCAN_T - 1) / SCAN_T;
    int lo = t * chunk;
    int hi = min(lo + chunk, N);

    int s = 0;
    for (int i = lo; i < hi; i++) s += g_cnt[i];
    part[t] = s;
    __syncthreads();

    for (int d = 1; d < SCAN_T; d <<= 1) {
        int v = (t >= d) ? part[t - d] : 0;
        __syncthreads();
        part[t] += v;
        __syncthreads();
    }

    int run = (t == 0) ? 0 : part[t - 1];
    for (int i = lo; i < hi; i++) {
        int c = g_cnt[i];
        g_off[i] = run;
        run += c;
        g_cnt[i] = 0;
    }
    if (hi == N && lo <= N) g_off[N] = run;
}

__global__ void fill_csr(const int* __restrict__ ei, int E) {
    int i = blockIdx.x * blockDim.x + threadIdx.x;
    if (i < E) {
        int dst = ei[E + i];
        int pos = g_off[dst] + atomicAdd(&g_cnt[dst], 1);
        g_srcs[pos] = ei[i];
    }
}

__global__ void convert_w(const float* __restrict__ W) {
    int i = blockIdx.x * blockDim.x + threadIdx.x;
    if (i < KTOT * C) {
        float v = W[i];
        __nv_bfloat16 hb = __float2bfloat16(v);
        float rem = v - __bfloat162float(hb);
        __nv_bfloat16 lb = __float2bfloat16(rem);
        g_Whi[i] = __bfloat16_as_ushort(hb);
        g_Wlo[i] = __bfloat16_as_ushort(lb);
    }
}

// Warp per node: max-reduce incoming x[src] rows, subtract x[n], write maxdiff.
__global__ void node_max(const float* __restrict__ x, int N) {
    int warp = (int)((blockIdx.x * (unsigned)blockDim.x + threadIdx.x) >> 5);
    int lane = threadIdx.x & 31;
    if (warp >= N) return;

    int begin = g_off[warp];
    int end   = g_off[warp + 1];

    float4 acc = make_float4(-CUDART_INF_F, -CUDART_INF_F, -CUDART_INF_F, -CUDART_INF_F);

    for (int base = begin; base < end; base += 32) {
        int j = base + lane;
        int s = (j < end) ? g_srcs[j] : 0;
        int cnt = min(end - base, 32);
        for (int t = 0; t < cnt; t++) {
            int src = __shfl_sync(0xffffffffu, s, t);
            float4 v = reinterpret_cast<const float4*>(x + (size_t)src * C)[lane];
            acc.x = fmaxf(acc.x, v.x);
            acc.y = fmaxf(acc.y, v.y);
            acc.z = fmaxf(acc.z, v.z);
            acc.w = fmaxf(acc.w, v.w);
        }
    }

    float4 o;
    if (end > begin) {
        float4 xn = reinterpret_cast<const float4*>(x + (size_t)warp * C)[lane];
        o.x = acc.x - xn.x;
        o.y = acc.y - xn.y;
        o.z = acc.z - xn.z;
        o.w = acc.w - xn.w;
    } else {
        o = make_float4(0.f, 0.f, 0.f, 0.f);
    }
    reinterpret_cast<float4*>(g_mdiff + (size_t)warp * C)[lane] = o;
}

// ---- tensor-core GEMM helpers ----
__device__ __forceinline__ void ldsm_x4(unsigned* r, const void* p) {
    unsigned a = (unsigned)__cvta_generic_to_shared(p);
    asm volatile("ldmatrix.sync.aligned.m8n8.x4.shared.b16 {%0,%1,%2,%3}, [%4];"
        : "=r"(r[0]), "=r"(r[1]), "=r"(r[2]), "=r"(r[3]) : "r"(a));
}
__device__ __forceinline__ void ldsm_x2_t(unsigned* r, const void* p) {
    unsigned a = (unsigned)__cvta_generic_to_shared(p);
    asm volatile("ldmatrix.sync.aligned.m8n8.x2.trans.shared.b16 {%0,%1}, [%2];"
        : "=r"(r[0]), "=r"(r[1]) : "r"(a));
}
__device__ __forceinline__ void mma_bf16(float* d, const unsigned* a, const unsigned* bf) {
    asm volatile("mma.sync.aligned.m16n8k16.row.col.f32.bf16.bf16.f32 "
        "{%0,%1,%2,%3}, {%4,%5,%6,%7}, {%8,%9}, {%0,%1,%2,%3};"
        : "+f"(d[0]), "+f"(d[1]), "+f"(d[2]), "+f"(d[3])
        : "r"(a[0]), "r"(a[1]), "r"(a[2]), "r"(a[3]), "r"(bf[0]), "r"(bf[1]));
}

// Pack two floats' bf16-hi parts into one 32-bit word (a -> low half, b -> high half).
__device__ __forceinline__ unsigned pack_hi2(float a, float b) {
    unsigned ha = (unsigned)__bfloat16_as_ushort(__float2bfloat16(a));
    unsigned hb = (unsigned)__bfloat16_as_ushort(__float2bfloat16(b));
    return ha | (hb << 16);
}
__device__ __forceinline__ unsigned pack_lo2(float a, float b) {
    float ra = a - __bfloat162float(__float2bfloat16(a));
    float rb = b - __bfloat162float(__float2bfloat16(b));
    unsigned la = (unsigned)__bfloat16_as_ushort(__float2bfloat16(ra));
    unsigned lb = (unsigned)__bfloat16_as_ushort(__float2bfloat16(rb));
    return la | (lb << 16);
}

// out[n] = [x[n] | mdiff[n]] @ W + b, bf16 split (3-term) tensor-core GEMM.
// Block: 128 rows x 128 cols; 8 warps, warp = 32 rows x 64 cols.
__global__ __launch_bounds__(256) void gemm_tc(const float* __restrict__ x,
                                               const float* __restrict__ b,
                                               float* __restrict__ out, int N) {
    __shared__ unsigned short As_hi[128][24];   // 48B row stride (16 used + 8 pad)
    __shared__ unsigned short As_lo[128][24];
    __shared__ unsigned short Bs_hi[16][136];   // 272B row stride (128 used + 8 pad)
    __shared__ unsigned short Bs_lo[16][136];

    int t    = threadIdx.x;
    int lane = t & 31;
    int wid  = t >> 5;
    int wr   = wid >> 1;          // 0..3 -> 32-row band
    int wc   = wid & 1;           // 0..1 -> 64-col band
    int row0 = blockIdx.x * 128;

    float acc[2][8][4];
#pragma unroll
    for (int mi = 0; mi < 2; mi++) {
#pragma unroll
        for (int ni = 0; ni < 8; ni++) {
#pragma unroll
            for (int r = 0; r < 4; r++) acc[mi][ni][r] = 0.f;
        }
    }

#pragma unroll 1
    for (int ks = 0; ks < 16; ks++) {
        // Stage A: 128 rows x 16 k (fp32 -> hi/lo bf16). 512 float4 loads, 2 per thread.
#pragma unroll
        for (int it = 0; it < 2; it++) {
            int idx = t + 256 * it;           // 0..511
            int r = idx >> 2;                 // 0..127
            int q = idx & 3;                  // float4 slot
            int row = row0 + r;
            float4 v = make_float4(0.f, 0.f, 0.f, 0.f);
            if (row < N) {
                if (ks < 8) v = *reinterpret_cast<const float4*>(x + (size_t)row * C + ks * 16 + q * 4);
                else        v = *reinterpret_cast<const float4*>(g_mdiff + (size_t)row * C + (ks - 8) * 16 + q * 4);
            }
            unsigned* dh = reinterpret_cast<unsigned*>(&As_hi[r][q * 4]);
            unsigned* dl = reinterpret_cast<unsigned*>(&As_lo[r][q * 4]);
            dh[0] = pack_hi2(v.x, v.y);
            dh[1] = pack_hi2(v.z, v.w);
            dl[0] = pack_lo2(v.x, v.y);
            dl[1] = pack_lo2(v.z, v.w);
        }
        // Stage B: 16 k x 128 n (pre-split bf16, uint4 copies; 256 threads cover both tiles)
        {
            int r  = t >> 4;                  // 0..15
            int c8 = t & 15;                  // 8-elem chunk
            uint4 wh = *reinterpret_cast<const uint4*>(g_Whi + (size_t)(ks * 16 + r) * C + c8 * 8);
            uint4 wl = *reinterpret_cast<const uint4*>(g_Wlo + (size_t)(ks * 16 + r) * C + c8 * 8);
            *reinterpret_cast<uint4*>(&Bs_hi[r][c8 * 8]) = wh;
            *reinterpret_cast<uint4*>(&Bs_lo[r][c8 * 8]) = wl;
        }
        __syncthreads();

        unsigned ahi[2][4];
        unsigned alo[2][4];
#pragma unroll
        for (int mi = 0; mi < 2; mi++) {
            int r = wr * 32 + mi * 16 + (lane & 15);
            int cb = (lane >> 4) * 8;
            ldsm_x4(ahi[mi], &As_hi[r][cb]);
            ldsm_x4(alo[mi], &As_lo[r][cb]);
        }
#pragma unroll
        for (int ni = 0; ni < 8; ni++) {
            int n0 = wc * 64 + ni * 8;
            unsigned bhi[2];
            unsigned blo[2];
            ldsm_x2_t(bhi, &Bs_hi[lane & 15][n0]);
            ldsm_x2_t(blo, &Bs_lo[lane & 15][n0]);
#pragma unroll
            for (int mi = 0; mi < 2; mi++) {
                mma_bf16(acc[mi][ni], ahi[mi], bhi);
                mma_bf16(acc[mi][ni], ahi[mi], blo);
                mma_bf16(acc[mi][ni], alo[mi], bhi);
            }
        }
        __syncthreads();
    }

    // Epilogue: d0,d1 -> (row lane/4, col +0/+1); d2,d3 -> (row lane/4+8)
#pragma unroll
    for (int ni = 0; ni < 8; ni++) {
        int col = wc * 64 + ni * 8 + (lane & 3) * 2;
        float2 bv = *reinterpret_cast<const float2*>(b + col);
#pragma unroll
        for (int mi = 0; mi < 2; mi++) {
            int r0 = row0 + wr * 32 + mi * 16 + (lane >> 2);
            if (r0 < N) {
                float2 o0 = make_float2(acc[mi][ni][0] + bv.x, acc[mi][ni][1] + bv.y);
                *reinterpret_cast<float2*>(out + (size_t)r0 * C + col) = o0;
            }
            int r1 = r0 + 8;
            if (r1 < N) {
                float2 o1 = make_float2(acc[mi][ni][2] + bv.x, acc[mi][ni][3] + bv.y);
                *reinterpret_cast<float2*>(out + (size_t)r1 * C + col) = o1;
            }
        }
    }
}

extern "C" void kernel_launch(void* const* d_in, const int* in_sizes, int n_in,
                              void* d_out, int out_size) {
    const float* x   = (const float*)d_in[0];
    const int*   ei  = (const int*)d_in[1];
    const float* W   = (const float*)d_in[2];
    const float* b   = (const float*)d_in[3];
    float*       out = (float*)d_out;

    int N = in_sizes[0] / C;      // 50000
    int E = in_sizes[1] / 2;      // 800000

    zero_counts<<<(N + 255) / 256, 256>>>(N);
    count_deg<<<(E + 255) / 256, 256>>>(ei, E);
    convert_w<<<(KTOT * C + 255) / 256, 256>>>(W);
    scan_offsets<<<1, SCAN_T>>>(N);
    fill_csr<<<(E + 255) / 256, 256>>>(ei, E);

    {
        long long threads = (long long)N * 32;
        int blocks = (int)((threads + 255) / 256);
        node_max<<<blocks, 256>>>(x, N);
    }
    gemm_tc<<<(N + 127) / 128, 256>>>(x, b, out, N);
}

// round 6
// speedup vs baseline: 3.8564x; 1.4795x over previous
#include <cuda_runtime.h>
#include <cuda_bf16.h>
#include <math_constants.h>
#include <cstdint>

#define C 128
#define MAXN 50000
#define MAXE 800000
#define KTOT 256
#define SCAN_BLK 1024
#define NBMAX 64

// CSR scratch
__device__ int   g_cnt[MAXN];       // in-degree counts (zeroed at end of each run)
__device__ int   g_cur[MAXN];       // fill cursors (zeroed before use each run)
__device__ int   g_off[MAXN + 1];   // exclusive offsets
__device__ int   g_srcs[MAXE];      // src ids grouped by dst
__device__ float g_mdiff[MAXN * C];
__device__ int   g_bsum[NBMAX];
__device__ int   g_boff[NBMAX];
// Split-precision W (hi/lo bf16), raw 16-bit words
__device__ unsigned short g_Whi[KTOT * C];
__device__ unsigned short g_Wlo[KTOT * C];

__global__ void count_deg(const int* __restrict__ ei, int E, int TT) {
    int t = blockIdx.x * blockDim.x + threadIdx.x;
#pragma unroll
    for (int j = 0; j < 4; j++) {
        int i = t + j * TT;
        if (i < E) atomicAdd(&g_cnt[__ldg(ei + E + i)], 1);
    }
}

__global__ void convert_w(const float* __restrict__ W) {
    int i = blockIdx.x * blockDim.x + threadIdx.x;
    if (i < KTOT * C) {
        float v = W[i];
        __nv_bfloat16 hb = __float2bfloat16(v);
        float rem = v - __bfloat162float(hb);
        __nv_bfloat16 lb = __float2bfloat16(rem);
        g_Whi[i] = __bfloat16_as_ushort(hb);
        g_Wlo[i] = __bfloat16_as_ushort(lb);
    }
}

// Phase 1: block-local exclusive scan (1024 threads/block) + block totals.
__global__ void scan1(int N) {
    __shared__ int wsum[32];
    int tid  = threadIdx.x;
    int lane = tid & 31;
    int wid  = tid >> 5;
    int i = blockIdx.x * SCAN_BLK + tid;
    int c = (i < N) ? g_cnt[i] : 0;

    int v = c;                                  // inclusive warp scan
#pragma unroll
    for (int d = 1; d < 32; d <<= 1) {
        int u = __shfl_up_sync(0xffffffffu, v, d);
        if (lane >= d) v += u;
    }
    if (lane == 31) wsum[wid] = v;
    __syncthreads();
    if (wid == 0) {
        int w = wsum[lane];                     // 32 warp totals
#pragma unroll
        for (int d = 1; d < 32; d <<= 1) {
            int u = __shfl_up_sync(0xffffffffu, w, d);
            if (lane >= d) w += u;
        }
        wsum[lane] = w;                         // inclusive over warps
    }
    __syncthreads();
    int base = (wid > 0) ? wsum[wid - 1] : 0;
    if (i < N) g_off[i] = base + v - c;         // exclusive prefix within block
    if (tid == SCAN_BLK - 1) g_bsum[blockIdx.x] = base + v;
}

// Phase 2: scan block sums (single tiny block), write grand total to g_off[N].
__global__ void scan2(int NB, int N) {
    __shared__ int s[NBMAX];
    int t = threadIdx.x;
    int v = (t < NB) ? g_bsum[t] : 0;
    s[t] = v;
    __syncthreads();
#pragma unroll
    for (int d = 1; d < NBMAX; d <<= 1) {
        int u = (t >= d) ? s[t - d] : 0;
        __syncthreads();
        s[t] += u;
        __syncthreads();
    }
    if (t < NB) g_boff[t] = s[t] - v;           // exclusive
    if (t == NBMAX - 1) g_off[N] = s[NBMAX - 1];
}

// Phase 3: add block offsets; zero counts and cursors for this run / next replay.
__global__ void scan3(int N) {
    int i = blockIdx.x * SCAN_BLK + threadIdx.x;
    if (i < N) {
        g_off[i] += g_boff[blockIdx.x];
        g_cnt[i] = 0;
        g_cur[i] = 0;
    }
}

__global__ void fill_csr(const int* __restrict__ ei, int E, int TT) {
    int t = blockIdx.x * blockDim.x + threadIdx.x;
#pragma unroll
    for (int j = 0; j < 4; j++) {
        int i = t + j * TT;
        if (i < E) {
            int dst = __ldg(ei + E + i);
            int src = __ldg(ei + i);
            int pos = g_off[dst] + atomicAdd(&g_cur[dst], 1);
            g_srcs[pos] = src;
        }
    }
}

// Warp per node: max-reduce incoming x[src] rows, subtract x[n], write maxdiff.
__global__ void node_max(const float* __restrict__ x, int N) {
    int warp = (int)((blockIdx.x * (unsigned)blockDim.x + threadIdx.x) >> 5);
    int lane = threadIdx.x & 31;
    if (warp >= N) return;

    int begin = g_off[warp];
    int end   = g_off[warp + 1];

    float4 acc = make_float4(-CUDART_INF_F, -CUDART_INF_F, -CUDART_INF_F, -CUDART_INF_F);

    for (int base = begin; base < end; base += 32) {
        int j = base + lane;
        int s = (j < end) ? g_srcs[j] : 0;
        int cnt = min(end - base, 32);
        for (int t = 0; t < cnt; t++) {
            int src = __shfl_sync(0xffffffffu, s, t);
            float4 v = reinterpret_cast<const float4*>(x + (size_t)src * C)[lane];
            acc.x = fmaxf(acc.x, v.x);
            acc.y = fmaxf(acc.y, v.y);
            acc.z = fmaxf(acc.z, v.z);
            acc.w = fmaxf(acc.w, v.w);
        }
    }

    float4 o;
    if (end > begin) {
        float4 xn = reinterpret_cast<const float4*>(x + (size_t)warp * C)[lane];
        o.x = acc.x - xn.x;
        o.y = acc.y - xn.y;
        o.z = acc.z - xn.z;
        o.w = acc.w - xn.w;
    } else {
        o = make_float4(0.f, 0.f, 0.f, 0.f);
    }
    reinterpret_cast<float4*>(g_mdiff + (size_t)warp * C)[lane] = o;
}

// ---- tensor-core GEMM helpers ----
__device__ __forceinline__ void ldsm_x4(unsigned* r, const void* p) {
    unsigned a = (unsigned)__cvta_generic_to_shared(p);
    asm volatile("ldmatrix.sync.aligned.m8n8.x4.shared.b16 {%0,%1,%2,%3}, [%4];"
        : "=r"(r[0]), "=r"(r[1]), "=r"(r[2]), "=r"(r[3]) : "r"(a));
}
__device__ __forceinline__ void ldsm_x2_t(unsigned* r, const void* p) {
    unsigned a = (unsigned)__cvta_generic_to_shared(p);
    asm volatile("ldmatrix.sync.aligned.m8n8.x2.trans.shared.b16 {%0,%1}, [%2];"
        : "=r"(r[0]), "=r"(r[1]) : "r"(a));
}
__device__ __forceinline__ void mma_bf16(float* d, const unsigned* a, const unsigned* bf) {
    asm volatile("mma.sync.aligned.m16n8k16.row.col.f32.bf16.bf16.f32 "
        "{%0,%1,%2,%3}, {%4,%5,%6,%7}, {%8,%9}, {%0,%1,%2,%3};"
        : "+f"(d[0]), "+f"(d[1]), "+f"(d[2]), "+f"(d[3])
        : "r"(a[0]), "r"(a[1]), "r"(a[2]), "r"(a[3]), "r"(bf[0]), "r"(bf[1]));
}

__device__ __forceinline__ unsigned pack_hi2(float a, float b) {
    unsigned ha = (unsigned)__bfloat16_as_ushort(__float2bfloat16(a));
    unsigned hb = (unsigned)__bfloat16_as_ushort(__float2bfloat16(b));
    return ha | (hb << 16);
}
__device__ __forceinline__ unsigned pack_lo2(float a, float b) {
    float ra = a - __bfloat162float(__float2bfloat16(a));
    float rb = b - __bfloat162float(__float2bfloat16(b));
    unsigned la = (unsigned)__bfloat16_as_ushort(__float2bfloat16(ra));
    unsigned lb = (unsigned)__bfloat16_as_ushort(__float2bfloat16(rb));
    return la | (lb << 16);
}

// out[n] = [x[n] | mdiff[n]] @ W + b, bf16 split (3-term) tensor-core GEMM.
// Block: 128 rows x 128 cols; 8 warps, warp = 32 rows x 64 cols.
__global__ __launch_bounds__(256) void gemm_tc(const float* __restrict__ x,
                                               const float* __restrict__ b,
                                               float* __restrict__ out, int N) {
    __shared__ unsigned short As_hi[128][24];   // 48B row stride
    __shared__ unsigned short As_lo[128][24];
    __shared__ unsigned short Bs_hi[16][136];   // 272B row stride
    __shared__ unsigned short Bs_lo[16][136];

    int t    = threadIdx.x;
    int lane = t & 31;
    int wid  = t >> 5;
    int wr   = wid >> 1;
    int wc   = wid & 1;
    int row0 = blockIdx.x * 128;

    float acc[2][8][4];
#pragma unroll
    for (int mi = 0; mi < 2; mi++) {
#pragma unroll
        for (int ni = 0; ni < 8; ni++) {
#pragma unroll
            for (int r = 0; r < 4; r++) acc[mi][ni][r] = 0.f;
        }
    }

#pragma unroll 1
    for (int ks = 0; ks < 16; ks++) {
#pragma unroll
        for (int it = 0; it < 2; it++) {
            int idx = t + 256 * it;
            int r = idx >> 2;
            int q = idx & 3;
            int row = row0 + r;
            float4 v = make_float4(0.f, 0.f, 0.f, 0.f);
            if (row < N) {
                if (ks < 8) v = *reinterpret_cast<const float4*>(x + (size_t)row * C + ks * 16 + q * 4);
                else        v = *reinterpret_cast<const float4*>(g_mdiff + (size_t)row * C + (ks - 8) * 16 + q * 4);
            }
            unsigned* dh = reinterpret_cast<unsigned*>(&As_hi[r][q * 4]);
            unsigned* dl = reinterpret_cast<unsigned*>(&As_lo[r][q * 4]);
            dh[0] = pack_hi2(v.x, v.y);
            dh[1] = pack_hi2(v.z, v.w);
            dl[0] = pack_lo2(v.x, v.y);
            dl[1] = pack_lo2(v.z, v.w);
        }
        {
            int r  = t >> 4;
            int c8 = t & 15;
            uint4 wh = *reinterpret_cast<const uint4*>(g_Whi + (size_t)(ks * 16 + r) * C + c8 * 8);
            uint4 wl = *reinterpret_cast<const uint4*>(g_Wlo + (size_t)(ks * 16 + r) * C + c8 * 8);
            *reinterpret_cast<uint4*>(&Bs_hi[r][c8 * 8]) = wh;
            *reinterpret_cast<uint4*>(&Bs_lo[r][c8 * 8]) = wl;
        }
        __syncthreads();

        unsigned ahi[2][4];
        unsigned alo[2][4];
#pragma unroll
        for (int mi = 0; mi < 2; mi++) {
            int r = wr * 32 + mi * 16 + (lane & 15);
            int cb = (lane >> 4) * 8;
            ldsm_x4(ahi[mi], &As_hi[r][cb]);
            ldsm_x4(alo[mi], &As_lo[r][cb]);
        }
#pragma unroll
        for (int ni = 0; ni < 8; ni++) {
            int n0 = wc * 64 + ni * 8;
            unsigned bhi[2];
            unsigned blo[2];
            ldsm_x2_t(bhi, &Bs_hi[lane & 15][n0]);
            ldsm_x2_t(blo, &Bs_lo[lane & 15][n0]);
#pragma unroll
            for (int mi = 0; mi < 2; mi++) {
                mma_bf16(acc[mi][ni], ahi[mi], bhi);
                mma_bf16(acc[mi][ni], ahi[mi], blo);
                mma_bf16(acc[mi][ni], alo[mi], bhi);
            }
        }
        __syncthreads();
    }

#pragma unroll
    for (int ni = 0; ni < 8; ni++) {
        int col = wc * 64 + ni * 8 + (lane & 3) * 2;
        float2 bv = *reinterpret_cast<const float2*>(b + col);
#pragma unroll
        for (int mi = 0; mi < 2; mi++) {
            int r0 = row0 + wr * 32 + mi * 16 + (lane >> 2);
            if (r0 < N) {
                float2 o0 = make_float2(acc[mi][ni][0] + bv.x, acc[mi][ni][1] + bv.y);
                *reinterpret_cast<float2*>(out + (size_t)r0 * C + col) = o0;
            }
            int r1 = r0 + 8;
            if (r1 < N) {
                float2 o1 = make_float2(acc[mi][ni][2] + bv.x, acc[mi][ni][3] + bv.y);
                *reinterpret_cast<float2*>(out + (size_t)r1 * C + col) = o1;
            }
        }
    }
}

extern "C" void kernel_launch(void* const* d_in, const int* in_sizes, int n_in,
                              void* d_out, int out_size) {
    const float* x   = (const float*)d_in[0];
    const int*   ei  = (const int*)d_in[1];
    const float* W   = (const float*)d_in[2];
    const float* b   = (const float*)d_in[3];
    float*       out = (float*)d_out;

    int N = in_sizes[0] / C;      // 50000
    int E = in_sizes[1] / 2;      // 800000
    int NB = (N + SCAN_BLK - 1) / SCAN_BLK;   // 49

    // g_cnt / g_cur are zero at first call (static init) and re-zeroed by scan3
    // each invocation, so no upfront zeroing kernel is needed.
    {
        int TT = (E + 3) / 4;
        count_deg<<<(TT + 255) / 256, 256>>>(ei, E, TT);
    }
    convert_w<<<(KTOT * C + 255) / 256, 256>>>(W);
    scan1<<<NB, SCAN_BLK>>>(N);
    scan2<<<1, NBMAX>>>(NB, N);
    scan3<<<NB, SCAN_BLK>>>(N);
    {
        int TT = (E + 3) / 4;
        fill_csr<<<(TT + 255) / 256, 256>>>(ei, E, TT);
    }
    {
        long long threads = (long long)N * 32;
        int blocks = (int)((threads + 255) / 256);
        node_max<<<blocks, 256>>>(x, N);
    }
    gemm_tc<<<(N + 127) / 128, 256>>>(x, b, out, N);
}

// round 8
// speedup vs baseline: 4.5572x; 1.1817x over previous
#include <cuda_runtime.h>
#include <cuda_bf16.h>
#include <math_constants.h>
#include <cstdint>

#define C 128
#define MAXN 50000
#define MAXE 800000
#define KTOT 256
#define SCAN_BLK 1024
#define NBMAX 64

// CSR scratch
__device__ int   g_cnt[MAXN];       // in-degree counts (re-zeroed inside scan_all)
__device__ int   g_cur[MAXN];       // fill cursors (re-zeroed inside scan_all)
__device__ int   g_off[MAXN + 1];   // exclusive offsets
__device__ int   g_srcs[MAXE];      // src ids grouped by dst
__device__ float g_mdiff[MAXN * C];
__device__ int   g_agg[NBMAX];      // per-block aggregates
__device__ unsigned g_bar;          // monotonic barrier counter (replay-safe)
// Split-precision W (hi/lo bf16), raw 16-bit words
__device__ unsigned short g_Whi[KTOT * C];
__device__ unsigned short g_Wlo[KTOT * C];

// Fused prep: edge-degree count (4-way ILP) + W hi/lo split.
__global__ void prep(const int* __restrict__ ei, int E, int TT,
                     const float* __restrict__ W) {
    int t = blockIdx.x * blockDim.x + threadIdx.x;
    if (t < KTOT * C) {
        float v = W[t];
        __nv_bfloat16 hb = __float2bfloat16(v);
        float rem = v - __bfloat162float(hb);
        __nv_bfloat16 lb = __float2bfloat16(rem);
        g_Whi[t] = __bfloat16_as_ushort(hb);
        g_Wlo[t] = __bfloat16_as_ushort(lb);
    }
#pragma unroll
    for (int j = 0; j < 4; j++) {
        int i = t + j * TT;
        if (i < E) atomicAdd(&g_cnt[__ldg(ei + E + i)], 1);
    }
}

// Single-kernel exclusive scan over g_cnt -> g_off, plus g_cnt/g_cur zeroing.
// Grid of NB (<=64) co-resident blocks; software grid barrier on a monotonic
// counter (generation derived from old/NB, so graph replays are safe).
__global__ void scan_all(int N) {
    __shared__ int wsum[32];
    __shared__ int s_boff;
    __shared__ int s_total;
    int NB   = gridDim.x;
    int tid  = threadIdx.x;
    int lane = tid & 31;
    int wid  = tid >> 5;
    int i = blockIdx.x * SCAN_BLK + tid;
    int c = (i < N) ? g_cnt[i] : 0;

    int v = c;                                  // inclusive warp scan
#pragma unroll
    for (int d = 1; d < 32; d <<= 1) {
        int u = __shfl_up_sync(0xffffffffu, v, d);
        if (lane >= d) v += u;
    }
    if (lane == 31) wsum[wid] = v;
    __syncthreads();
    if (wid == 0) {
        int w = wsum[lane];
#pragma unroll
        for (int d = 1; d < 32; d <<= 1) {
            int u = __shfl_up_sync(0xffffffffu, w, d);
            if (lane >= d) w += u;
        }
        wsum[lane] = w;                         // inclusive over warps
    }
    __syncthreads();
    int base = (wid > 0) ? wsum[wid - 1] : 0;
    int excl = base + v - c;                    // block-local exclusive prefix

    // publish aggregate + software grid barrier
    if (tid == 0) {
        g_agg[blockIdx.x] = wsum[31];
        __threadfence();
        unsigned old = atomicAdd(&g_bar, 1u);
        unsigned gen = old / (unsigned)NB;
        unsigned tgt = (gen + 1u) * (unsigned)NB;
        while (atomicAdd(&g_bar, 0u) < tgt) { }
        __threadfence();
    }
    __syncthreads();

    // every block sums all aggregates (NB <= 64)
    if (wid == 0) {
        int bid = blockIdx.x;
        int pre = 0;
        int tot = 0;
        for (int j = lane; j < NB; j += 32) {
            int a = atomicAdd(&g_agg[j], 0);    // ordered read
            tot += a;
            if (j < bid) pre += a;
        }
#pragma unroll
        for (int d = 16; d > 0; d >>= 1) {
            pre += __shfl_down_sync(0xffffffffu, pre, d);
            tot += __shfl_down_sync(0xffffffffu, tot, d);
        }
        if (lane == 0) { s_boff = pre; s_total = tot; }
    }
    __syncthreads();

    if (i < N) {
        g_off[i] = s_boff + excl;
        g_cnt[i] = 0;
        g_cur[i] = 0;
    }
    if (blockIdx.x == 0 && tid == 0) g_off[N] = s_total;
}

__global__ void fill_csr(const int* __restrict__ ei, int E, int TT) {
    int t = blockIdx.x * blockDim.x + threadIdx.x;
#pragma unroll
    for (int j = 0; j < 4; j++) {
        int i = t + j * TT;
        if (i < E) {
            int dst = __ldg(ei + E + i);
            int src = __ldg(ei + i);
            int pos = g_off[dst] + atomicAdd(&g_cur[dst], 1);
            g_srcs[pos] = src;
        }
    }
}

// Warp per node: max-reduce incoming x[src] rows, subtract x[n], write maxdiff.
__global__ void node_max(const float* __restrict__ x, int N) {
    int warp = (int)((blockIdx.x * (unsigned)blockDim.x + threadIdx.x) >> 5);
    int lane = threadIdx.x & 31;
    if (warp >= N) return;

    int begin = g_off[warp];
    int end   = g_off[warp + 1];

    float4 acc = make_float4(-CUDART_INF_F, -CUDART_INF_F, -CUDART_INF_F, -CUDART_INF_F);

    for (int base = begin; base < end; base += 32) {
        int j = base + lane;
        int s = (j < end) ? g_srcs[j] : 0;
        int cnt = min(end - base, 32);
        for (int t = 0; t < cnt; t++) {
            int src = __shfl_sync(0xffffffffu, s, t);
            float4 v = reinterpret_cast<const float4*>(x + (size_t)src * C)[lane];
            acc.x = fmaxf(acc.x, v.x);
            acc.y = fmaxf(acc.y, v.y);
            acc.z = fmaxf(acc.z, v.z);
            acc.w = fmaxf(acc.w, v.w);
        }
    }

    float4 o;
    if (end > begin) {
        float4 xn = reinterpret_cast<const float4*>(x + (size_t)warp * C)[lane];
        o.x = acc.x - xn.x;
        o.y = acc.y - xn.y;
        o.z = acc.z - xn.z;
        o.w = acc.w - xn.w;
    } else {
        o = make_float4(0.f, 0.f, 0.f, 0.f);
    }
    reinterpret_cast<float4*>(g_mdiff + (size_t)warp * C)[lane] = o;
}

// ---- tensor-core GEMM helpers ----
__device__ __forceinline__ void ldsm_x4(unsigned* r, const void* p) {
    unsigned a = (unsigned)__cvta_generic_to_shared(p);
    asm volatile("ldmatrix.sync.aligned.m8n8.x4.shared.b16 {%0,%1,%2,%3}, [%4];"
        : "=r"(r[0]), "=r"(r[1]), "=r"(r[2]), "=r"(r[3]) : "r"(a));
}
__device__ __forceinline__ void ldsm_x2_t(unsigned* r, const void* p) {
    unsigned a = (unsigned)__cvta_generic_to_shared(p);
    asm volatile("ldmatrix.sync.aligned.m8n8.x2.trans.shared.b16 {%0,%1}, [%2];"
        : "=r"(r[0]), "=r"(r[1]) : "r"(a));
}
__device__ __forceinline__ void mma_bf16(float* d, const unsigned* a, const unsigned* bf) {
    asm volatile("mma.sync.aligned.m16n8k16.row.col.f32.bf16.bf16.f32 "
        "{%0,%1,%2,%3}, {%4,%5,%6,%7}, {%8,%9}, {%0,%1,%2,%3};"
        : "+f"(d[0]), "+f"(d[1]), "+f"(d[2]), "+f"(d[3])
        : "r"(a[0]), "r"(a[1]), "r"(a[2]), "r"(a[3]), "r"(bf[0]), "r"(bf[1]));
}
__device__ __forceinline__ void cp16(void* smem, const void* gmem) {
    unsigned a = (unsigned)__cvta_generic_to_shared(smem);
    asm volatile("cp.async.cg.shared.global [%0], [%1], 16;" :: "r"(a), "l"(gmem));
}
__device__ __forceinline__ void cp_commit() {
    asm volatile("cp.async.commit_group;");
}
template <int NN>
__device__ __forceinline__ void cp_wait() {
    asm volatile("cp.async.wait_group %0;" :: "n"(NN));
}

__device__ __forceinline__ unsigned pack_hi2(float a, float b) {
    unsigned ha = (unsigned)__bfloat16_as_ushort(__float2bfloat16(a));
    unsigned hb = (unsigned)__bfloat16_as_ushort(__float2bfloat16(b));
    return ha | (hb << 16);
}
__device__ __forceinline__ unsigned pack_lo2(float a, float b) {
    float ra = a - __bfloat162float(__float2bfloat16(a));
    float rb = b - __bfloat162float(__float2bfloat16(b));
    unsigned la = (unsigned)__bfloat16_as_ushort(__float2bfloat16(ra));
    unsigned lb = (unsigned)__bfloat16_as_ushort(__float2bfloat16(rb));
    return la | (lb << 16);
}

// out[n] = [x[n] | mdiff[n]] @ W + b, bf16 split (3-term) tensor-core GEMM.
// Block 128x128, 8 warps (32x64 each); 2-stage double buffer.
// RACE-SAFE schedule: ALL writes into buffer `nxt` (cp.async B prefetch and
// A convert/store) are issued only AFTER this iteration's __syncthreads(),
// which guarantees every warp has finished reading `nxt` from the previous
// iteration.
__global__ __launch_bounds__(256) void gemm_tc(const float* __restrict__ x,
                                               const float* __restrict__ b,
                                               float* __restrict__ out, int N) {
    __shared__ unsigned short As_hi[2][128][24];
    __shared__ unsigned short As_lo[2][128][24];
    __shared__ unsigned short Bs_hi[2][16][136];
    __shared__ unsigned short Bs_lo[2][16][136];

    int t    = threadIdx.x;
    int lane = t & 31;
    int wid  = t >> 5;
    int wr   = wid >> 1;
    int wc   = wid & 1;
    int row0 = blockIdx.x * 128;

    // A staging geometry (2 float4 per thread)
    int ar[2], aq[2];
#pragma unroll
    for (int it = 0; it < 2; it++) {
        int idx = t + 256 * it;
        ar[it] = idx >> 2;
        aq[it] = idx & 3;
    }
    // B staging geometry (1 hi + 1 lo 16B chunk per thread)
    int br  = t >> 4;
    int bc8 = t & 15;

    float4 va[2];

    auto loadA = [&](int ks) {
#pragma unroll
        for (int it = 0; it < 2; it++) {
            int row = row0 + ar[it];
            float4 v = make_float4(0.f, 0.f, 0.f, 0.f);
            if (row < N) {
                if (ks < 8) v = *reinterpret_cast<const float4*>(x + (size_t)row * C + ks * 16 + aq[it] * 4);
                else        v = *reinterpret_cast<const float4*>(g_mdiff + (size_t)row * C + (ks - 8) * 16 + aq[it] * 4);
            }
            va[it] = v;
        }
    };
    auto storeA = [&](int buf) {
#pragma unroll
        for (int it = 0; it < 2; it++) {
            unsigned* dh = reinterpret_cast<unsigned*>(&As_hi[buf][ar[it]][aq[it] * 4]);
            unsigned* dl = reinterpret_cast<unsigned*>(&As_lo[buf][ar[it]][aq[it] * 4]);
            dh[0] = pack_hi2(va[it].x, va[it].y);
            dh[1] = pack_hi2(va[it].z, va[it].w);
            dl[0] = pack_lo2(va[it].x, va[it].y);
            dl[1] = pack_lo2(va[it].z, va[it].w);
        }
    };
    auto loadB = [&](int ks, int buf) {
        const unsigned short* sh = g_Whi + (size_t)(ks * 16 + br) * C + bc8 * 8;
        const unsigned short* sl = g_Wlo + (size_t)(ks * 16 + br) * C + bc8 * 8;
        cp16(&Bs_hi[buf][br][bc8 * 8], sh);
        cp16(&Bs_lo[buf][br][bc8 * 8], sl);
    };

    float acc[2][8][4];
#pragma unroll
    for (int mi = 0; mi < 2; mi++) {
#pragma unroll
        for (int ni = 0; ni < 8; ni++) {
#pragma unroll
            for (int r = 0; r < 4; r++) acc[mi][ni][r] = 0.f;
        }
    }

    // prologue: stage chunk 0 into buf 0
    loadA(0);
    loadB(0, 0);
    cp_commit();
    storeA(0);

#pragma unroll 1
    for (int ks = 0; ks < 16; ks++) {
        int cur = ks & 1;
        int nxt = cur ^ 1;

        cp_wait<0>();               // chunk-cur B copy (committed last iter) done
        __syncthreads();            // cur fully staged; everyone done reading nxt

        if (ks < 15) {
            loadA(ks + 1);          // global->reg loads, overlap with MMAs below
            loadB(ks + 1, nxt);     // cp.async into nxt — safe: post-barrier
            cp_commit();
        }

        unsigned ahi[2][4];
        unsigned alo[2][4];
#pragma unroll
        for (int mi = 0; mi < 2; mi++) {
            int r = wr * 32 + mi * 16 + (lane & 15);
            int cb = (lane >> 4) * 8;
            ldsm_x4(ahi[mi], &As_hi[cur][r][cb]);
            ldsm_x4(alo[mi], &As_lo[cur][r][cb]);
        }
#pragma unroll
        for (int ni = 0; ni < 8; ni++) {
            int n0 = wc * 64 + ni * 8;
            unsigned bhi[2];
            unsigned blo[2];
            ldsm_x2_t(bhi, &Bs_hi[cur][lane & 15][n0]);
            ldsm_x2_t(blo, &Bs_lo[cur][lane & 15][n0]);
#pragma unroll
            for (int mi = 0; mi < 2; mi++) {
                mma_bf16(acc[mi][ni], ahi[mi], bhi);
                mma_bf16(acc[mi][ni], ahi[mi], blo);
                mma_bf16(acc[mi][ni], alo[mi], bhi);
            }
        }

        if (ks < 15) storeA(nxt);   // convert + st.shared into nxt (post-barrier)
    }

#pragma unroll
    for (int ni = 0; ni < 8; ni++) {
        int col = wc * 64 + ni * 8 + (lane & 3) * 2;
        float2 bv = *reinterpret_cast<const float2*>(b + col);
#pragma unroll
        for (int mi = 0; mi < 2; mi++) {
            int r0 = row0 + wr * 32 + mi * 16 + (lane >> 2);
            if (r0 < N) {
                float2 o0 = make_float2(acc[mi][ni][0] + bv.x, acc[mi][ni][1] + bv.y);
                *reinterpret_cast<float2*>(out + (size_t)r0 * C + col) = o0;
            }
            int r1 = r0 + 8;
            if (r1 < N) {
                float2 o1 = make_float2(acc[mi][ni][2] + bv.x, acc[mi][ni][3] + bv.y);
                *reinterpret_cast<float2*>(out + (size_t)r1 * C + col) = o1;
            }
        }
    }
}

extern "C" void kernel_launch(void* const* d_in, const int* in_sizes, int n_in,
                              void* d_out, int out_size) {
    const float* x   = (const float*)d_in[0];
    const int*   ei  = (const int*)d_in[1];
    const float* W   = (const float*)d_in[2];
    const float* b   = (const float*)d_in[3];
    float*       out = (float*)d_out;

    int N = in_sizes[0] / C;      // 50000
    int E = in_sizes[1] / 2;      // 800000
    int NB = (N + SCAN_BLK - 1) / SCAN_BLK;   // 49
    int TT = (E + 3) / 4;

    prep<<<(TT + 255) / 256, 256>>>(ei, E, TT, W);
    scan_all<<<NB, SCAN_BLK>>>(N);
    fill_csr<<<(TT + 255) / 256, 256>>>(ei, E, TT);
    {
        long long threads = (long long)N * 32;
        int blocks = (int)((threads + 255) / 256);
        node_max<<<blocks, 256>>>(x, N);
    }
    gemm_tc<<<(N + 127) / 128, 256>>>(x, b, out, N);
}